// round 12
// baseline (speedup 1.0000x reference)
#include <cuda_runtime.h>
#include <cuda_bf16.h>
#include <cstdint>
#include <cstddef>

#define BATCH 8
#define SEQ   2048
#define DIM   1024
#define MTOT  (BATCH*SEQ)   // 16384
#define NQKV  (3*DIM)       // 3072

#define BM 128
#define BN 128
#define BK 64
#define KSTRIDE 72                        // NT: halves per smem row (64 data + 8 pad)
#define NSTRIDE 136                       // NN B tile: 128 cols + 8 pad
#define A_TILE_HALVES (BM*KSTRIDE)        // 9216
#define STAGE_HALVES (2*A_TILE_HALVES)    // A + B slot (B uses <= 9216: NT 9216, NN 8704)
#define STAGE_BYTES (STAGE_HALVES*2)      // 36864
#define STAGES 3

// ---- scratch (device globals; allocation-free per harness rules) ----
__device__ __nv_bfloat16 g_xb[(size_t)MTOT*DIM];
__device__ __nv_bfloat16 g_Wqkvb[(size_t)NQKV*DIM];
__device__ __nv_bfloat16 g_Wob[DIM*DIM];
__device__ float         g_bqkv[NQKV];
__device__ __nv_bfloat16 g_QKV[(size_t)MTOT*NQKV];
__device__ float         g_S [(size_t)BATCH*SEQ*SEQ];
__device__ __nv_bfloat16 g_P [(size_t)BATCH*SEQ*SEQ];
__device__ __nv_bfloat16 g_Wt[(size_t)MTOT*DIM];

// ---- helpers ----
__device__ __forceinline__ void cp16(uint32_t saddr, const void* gmem) {
    asm volatile("cp.async.cg.shared.global [%0], [%1], 16;\n" :: "r"(saddr), "l"(gmem));
}
__device__ __forceinline__ void cp_commit() { asm volatile("cp.async.commit_group;\n"); }
template<int N> __device__ __forceinline__ void cp_wait() {
    asm volatile("cp.async.wait_group %0;\n" :: "n"(N));
}
__device__ __forceinline__ void ldsm_x4(uint32_t& r0, uint32_t& r1, uint32_t& r2, uint32_t& r3,
                                        uint32_t addr) {
    asm volatile("ldmatrix.sync.aligned.m8n8.x4.shared.b16 {%0,%1,%2,%3}, [%4];"
                 : "=r"(r0), "=r"(r1), "=r"(r2), "=r"(r3) : "r"(addr));
}
__device__ __forceinline__ void ldsm_x4_t(uint32_t& r0, uint32_t& r1, uint32_t& r2, uint32_t& r3,
                                          uint32_t addr) {
    asm volatile("ldmatrix.sync.aligned.m8n8.x4.trans.shared.b16 {%0,%1,%2,%3}, [%4];"
                 : "=r"(r0), "=r"(r1), "=r"(r2), "=r"(r3) : "r"(addr));
}
__device__ __forceinline__ void mma_bf16(float c[4], const uint32_t a[4], const uint32_t b[2]) {
    asm("mma.sync.aligned.m16n8k16.row.col.f32.bf16.bf16.f32 "
        "{%0,%1,%2,%3},{%4,%5,%6,%7},{%8,%9},{%0,%1,%2,%3};"
        : "+f"(c[0]), "+f"(c[1]), "+f"(c[2]), "+f"(c[3])
        : "r"(a[0]), "r"(a[1]), "r"(a[2]), "r"(a[3]), "r"(b[0]), "r"(b[1]));
}

// ---- bf16 GEMM: C = A[M,K] * op(B) * scale (+bias) (+resid) ----
// TRANSB=true : B is [N,K] row-major (C = A B^T), ldmatrix non-trans.
// TRANSB=false: B is [K,N] row-major (C = A B),   ldmatrix .trans.
// 128 threads / 4 warps (64x64 warp tiles), BK=64, 3-stage cp.async, 1 sync/iter.
template<typename OutT, bool HAS_BIAS, bool HAS_RESID, bool TRANSB>
__global__ __launch_bounds__(128, 2) void gemm_bf(
    const __nv_bfloat16* __restrict__ A, const __nv_bfloat16* __restrict__ B,
    const float* __restrict__ bias, const float* __restrict__ resid,
    OutT* __restrict__ C,
    int lda, int ldb, int ldc, int K, float scale,
    long sA, long sB, long sC)
{
    extern __shared__ __align__(16) __nv_bfloat16 smem[];  // STAGES*(As+Bs)

    const int bz = blockIdx.z;
    A += (long)bz * sA;
    B += (long)bz * sB;
    C += (long)bz * sC;

    const int m0 = blockIdx.y * BM;
    const int n0 = blockIdx.x * BN;
    const int tid  = threadIdx.x;
    const int wid  = tid >> 5;
    const int lane = tid & 31;
    const int wm = (wid >> 1) * 64;   // 2 warps in m
    const int wn = (wid & 1) * 64;    // 2 warps in n
    const int lg = lane >> 2;
    const int lq = lane & 3;

    // NT loader mapping: 8 threads/row (16B chunks), 16 rows/pass
    const int lr = tid >> 3;          // 0..15
    const int lc = (tid & 7) * 8;     // half offset 0..56
    // NN B loader mapping: 16 threads/row (16B chunks), 8 rows/pass
    const int lr16 = tid >> 4;        // 0..7
    const int lc16 = (tid & 15) * 8;  // half offset 0..120

    // ldmatrix lane address components
    const int a_row = wm + (lane & 15);                           // + i*16
    const int a_ksel = (lane >> 4) * 8;                           // + s*16
    // NT B: rows = n, cols = k
    const int b_row = wn + (lane & 7) + ((lane >> 4) & 1) * 8;    // + jp*16
    const int b_ksel = ((lane >> 3) & 1) * 8;
    // NN B (.trans): rows = k, cols = n
    const int bt_krow = (lane & 7) + ((lane >> 3) & 1) * 8;       // + s*16
    const int bt_ncol = wn + ((lane >> 4) & 1) * 8;               // + jp*16

    const uint32_t smem_base = (uint32_t)__cvta_generic_to_shared(smem);

    float acc[4][8][4];
#pragma unroll
    for (int i = 0; i < 4; i++)
#pragma unroll
        for (int j = 0; j < 8; j++)
#pragma unroll
            for (int r = 0; r < 4; r++) acc[i][j][r] = 0.f;

    const int KT = K / BK;

    auto load_stage = [&](int buf, int kt) {
        const int k0 = kt * BK;
        const uint32_t as = smem_base + buf * STAGE_BYTES;
        const uint32_t bs = as + A_TILE_HALVES * 2;
#pragma unroll
        for (int p = 0; p < 8; p++) {   // A: 128 rows x 64 halves
            int row = lr + p * 16;
            cp16(as + (row * KSTRIDE + lc) * 2, A + (long)(m0 + row) * lda + k0 + lc);
        }
        if (TRANSB) {
#pragma unroll
            for (int p = 0; p < 8; p++) {   // B: 128 n-rows x 64 halves
                int row = lr + p * 16;
                cp16(bs + (row * KSTRIDE + lc) * 2, B + (long)(n0 + row) * ldb + k0 + lc);
            }
        } else {
#pragma unroll
            for (int p = 0; p < 8; p++) {   // B: 64 k-rows x 128 halves
                int row = lr16 + p * 8;
                cp16(bs + (row * NSTRIDE + lc16) * 2, B + (long)(k0 + row) * ldb + n0 + lc16);
            }
        }
        cp_commit();
    };

    // prologue: fill 2 stages
    load_stage(0, 0);
    load_stage(1, 1);

    for (int kt = 0; kt < KT; kt++) {
        const int buf = kt % STAGES;
        cp_wait<1>();
        __syncthreads();   // all warps done with compute kt-1; buffer (kt+2)%3 is free

        if (kt + 2 < KT) load_stage((kt + 2) % STAGES, kt + 2);

        const uint32_t as = smem_base + buf * STAGE_BYTES;
        const uint32_t bs = as + A_TILE_HALVES * 2;

#pragma unroll
        for (int s = 0; s < 4; s++) {
            uint32_t af[4][4];
            uint32_t bfr[8][2];
#pragma unroll
            for (int i = 0; i < 4; i++) {
                uint32_t addr = as + (((a_row + i * 16) * KSTRIDE) + s * 16 + a_ksel) * 2;
                ldsm_x4(af[i][0], af[i][1], af[i][2], af[i][3], addr);
            }
#pragma unroll
            for (int jp = 0; jp < 4; jp++) {
                if (TRANSB) {
                    uint32_t addr = bs + (((b_row + jp * 16) * KSTRIDE) + s * 16 + b_ksel) * 2;
                    ldsm_x4(bfr[jp * 2][0], bfr[jp * 2][1],
                            bfr[jp * 2 + 1][0], bfr[jp * 2 + 1][1], addr);
                } else {
                    uint32_t addr = bs + (((s * 16 + bt_krow) * NSTRIDE) + bt_ncol + jp * 16) * 2;
                    ldsm_x4_t(bfr[jp * 2][0], bfr[jp * 2][1],
                              bfr[jp * 2 + 1][0], bfr[jp * 2 + 1][1], addr);
                }
            }
#pragma unroll
            for (int i = 0; i < 4; i++)
#pragma unroll
                for (int j = 0; j < 8; j++)
                    mma_bf16(acc[i][j], af[i], bfr[j]);
        }
    }

    // epilogue
#pragma unroll
    for (int i = 0; i < 4; i++) {
        int r = m0 + wm + i * 16 + lg;
#pragma unroll
        for (int j = 0; j < 8; j++) {
            int c = n0 + wn + j * 8 + lq * 2;
            float v0 = acc[i][j][0] * scale;
            float v1 = acc[i][j][1] * scale;
            float v2 = acc[i][j][2] * scale;
            float v3 = acc[i][j][3] * scale;
            if (HAS_BIAS) {
                float b0 = bias[c], b1 = bias[c + 1];
                v0 += b0; v1 += b1; v2 += b0; v3 += b1;
            }
            if (HAS_RESID) {
                v0 += resid[(long)r * ldc + c];
                v1 += resid[(long)r * ldc + c + 1];
                v2 += resid[(long)(r + 8) * ldc + c];
                v3 += resid[(long)(r + 8) * ldc + c + 1];
            }
            if constexpr (sizeof(OutT) == 2) {
                *reinterpret_cast<__nv_bfloat162*>(&C[(long)r * ldc + c]) =
                    __floats2bfloat162_rn(v0, v1);
                *reinterpret_cast<__nv_bfloat162*>(&C[(long)(r + 8) * ldc + c]) =
                    __floats2bfloat162_rn(v2, v3);
            } else {
                *reinterpret_cast<float2*>(&C[(long)r * ldc + c])       = make_float2(v0, v1);
                *reinterpret_cast<float2*>(&C[(long)(r + 8) * ldc + c]) = make_float2(v2, v3);
            }
        }
    }
}

// ---- fp32 -> bf16 convert ----
__global__ __launch_bounds__(256) void cvt_k(const float* __restrict__ in,
                                             __nv_bfloat16* __restrict__ out, int n)
{
    int i = (blockIdx.x * 256 + threadIdx.x) * 4;
    if (i < n) {
        float4 v = *reinterpret_cast<const float4*>(in + i);
        *reinterpret_cast<__nv_bfloat162*>(out + i)     = __floats2bfloat162_rn(v.x, v.y);
        *reinterpret_cast<__nv_bfloat162*>(out + i + 2) = __floats2bfloat162_rn(v.z, v.w);
    }
}

// ---- convert 3 weight matrices into concatenated bf16 buffer (1 launch) ----
__global__ __launch_bounds__(256) void cvt_w3_k(const float* __restrict__ w0,
                                                const float* __restrict__ w1,
                                                const float* __restrict__ w2,
                                                __nv_bfloat16* __restrict__ out)
{
    const int per = DIM * DIM / 4 / 256;          // blocks per matrix (1024)
    const int mat = blockIdx.x / per;
    const int blk = blockIdx.x % per;
    const float* src = (mat == 0) ? w0 : (mat == 1) ? w1 : w2;
    int i = (blk * 256 + threadIdx.x) * 4;
    float4 v = *reinterpret_cast<const float4*>(src + i);
    __nv_bfloat16* dst = out + (size_t)mat * DIM * DIM + i;
    *reinterpret_cast<__nv_bfloat162*>(dst)     = __floats2bfloat162_rn(v.x, v.y);
    *reinterpret_cast<__nv_bfloat162*>(dst + 2) = __floats2bfloat162_rn(v.z, v.w);
}

// ---- pack 3 bias vectors into one ----
__global__ __launch_bounds__(256) void pack_bias_k(const float* __restrict__ b0,
                                                   const float* __restrict__ b1,
                                                   const float* __restrict__ b2,
                                                   float* __restrict__ out)
{
    int i = blockIdx.x * 256 + threadIdx.x;   // grid 12 * 256 = 3072
    out[i] = (i < DIM) ? b0[i] : (i < 2 * DIM) ? b1[i - DIM] : b2[i - 2 * DIM];
}

// ---- row softmax (fp32 in, bf16 out), row length 2048 ----
__global__ __launch_bounds__(256) void softmax_k(const float* __restrict__ S,
                                                 __nv_bfloat16* __restrict__ P)
{
    const float* pin = S + (long)blockIdx.x * SEQ;
    __nv_bfloat16* pout = P + (long)blockIdx.x * SEQ;
    const int tid = threadIdx.x;
    float vals[8];
    float mx = -1e30f;
#pragma unroll
    for (int i = 0; i < 8; i++) {
        vals[i] = pin[tid + i * 256];
        mx = fmaxf(mx, vals[i]);
    }
#pragma unroll
    for (int o = 16; o; o >>= 1) mx = fmaxf(mx, __shfl_xor_sync(0xFFFFFFFFu, mx, o));
    __shared__ float redm[8];
    if ((tid & 31) == 0) redm[tid >> 5] = mx;
    __syncthreads();
    mx = redm[0];
#pragma unroll
    for (int i = 1; i < 8; i++) mx = fmaxf(mx, redm[i]);

    float sum = 0.f;
#pragma unroll
    for (int i = 0; i < 8; i++) {
        vals[i] = expf(vals[i] - mx);
        sum += vals[i];
    }
#pragma unroll
    for (int o = 16; o; o >>= 1) sum += __shfl_xor_sync(0xFFFFFFFFu, sum, o);
    __shared__ float reds[8];
    if ((tid & 31) == 0) reds[tid >> 5] = sum;
    __syncthreads();
    sum = 0.f;
#pragma unroll
    for (int i = 0; i < 8; i++) sum += reds[i];
    const float inv = 1.f / sum;
#pragma unroll
    for (int i = 0; i < 8; i++) pout[tid + i * 256] = __float2bfloat16(vals[i] * inv);
}

// ---- in-place LayerNorm over rows of 1024 fp32 ----
__global__ __launch_bounds__(256) void ln_k(float* __restrict__ y,
                                            const float* __restrict__ gamma,
                                            const float* __restrict__ beta)
{
    float* p = y + (long)blockIdx.x * DIM;
    const int tid = threadIdx.x;
    float4 v = reinterpret_cast<float4*>(p)[tid];
    float s  = v.x + v.y + v.z + v.w;
    float sq = v.x * v.x + v.y * v.y + v.z * v.z + v.w * v.w;
#pragma unroll
    for (int o = 16; o; o >>= 1) {
        s  += __shfl_xor_sync(0xFFFFFFFFu, s, o);
        sq += __shfl_xor_sync(0xFFFFFFFFu, sq, o);
    }
    __shared__ float rs_[8], rq_[8];
    if ((tid & 31) == 0) { rs_[tid >> 5] = s; rq_[tid >> 5] = sq; }
    __syncthreads();
    s = 0.f; sq = 0.f;
#pragma unroll
    for (int i = 0; i < 8; i++) { s += rs_[i]; sq += rq_[i]; }
    const float mean = s * (1.f / DIM);
    const float var  = sq * (1.f / DIM) - mean * mean;
    const float inv  = rsqrtf(var + 1e-5f);
    const float4 g = reinterpret_cast<const float4*>(gamma)[tid];
    const float4 b = reinterpret_cast<const float4*>(beta)[tid];
    v.x = (v.x - mean) * inv * g.x + b.x;
    v.y = (v.y - mean) * inv * g.y + b.y;
    v.z = (v.z - mean) * inv * g.z + b.z;
    v.w = (v.w - mean) * inv * g.w + b.w;
    reinterpret_cast<float4*>(p)[tid] = v;
}

extern "C" void kernel_launch(void* const* d_in, const int* in_sizes, int n_in,
                              void* d_out, int out_size)
{
    const float* x     = (const float*)d_in[0];
    const float* Wq    = (const float*)d_in[1];
    const float* bq    = (const float*)d_in[2];
    const float* Wk    = (const float*)d_in[3];
    const float* bk    = (const float*)d_in[4];
    const float* Wv    = (const float*)d_in[5];
    const float* bv    = (const float*)d_in[6];
    const float* Wo    = (const float*)d_in[7];
    const float* bo    = (const float*)d_in[8];
    const float* gamma = (const float*)d_in[9];
    const float* beta  = (const float*)d_in[10];
    float* out = (float*)d_out;

    void *pxb, *pwqkv, *pwo, *pbqkv, *pQKV, *pS, *pP, *pW;
    cudaGetSymbolAddress(&pxb,   g_xb);
    cudaGetSymbolAddress(&pwqkv, g_Wqkvb);
    cudaGetSymbolAddress(&pwo,   g_Wob);
    cudaGetSymbolAddress(&pbqkv, g_bqkv);
    cudaGetSymbolAddress(&pQKV,  g_QKV);
    cudaGetSymbolAddress(&pS,    g_S);
    cudaGetSymbolAddress(&pP,    g_P);
    cudaGetSymbolAddress(&pW,    g_Wt);
    __nv_bfloat16* xb    = (__nv_bfloat16*)pxb;
    __nv_bfloat16* Wqkvb = (__nv_bfloat16*)pwqkv;
    __nv_bfloat16* Wob   = (__nv_bfloat16*)pwo;
    float*         bqkv  = (float*)pbqkv;
    __nv_bfloat16* QKV   = (__nv_bfloat16*)pQKV;
    float*         Sc    = (float*)pS;
    __nv_bfloat16* P     = (__nv_bfloat16*)pP;
    __nv_bfloat16* Wt    = (__nv_bfloat16*)pW;

    const int SMEM = STAGES * STAGE_BYTES;  // 110592
    cudaFuncSetAttribute(gemm_bf<__nv_bfloat16, true,  false, true >, cudaFuncAttributeMaxDynamicSharedMemorySize, SMEM);
    cudaFuncSetAttribute(gemm_bf<float,         false, false, true >, cudaFuncAttributeMaxDynamicSharedMemorySize, SMEM);
    cudaFuncSetAttribute(gemm_bf<__nv_bfloat16, false, false, false>, cudaFuncAttributeMaxDynamicSharedMemorySize, SMEM);
    cudaFuncSetAttribute(gemm_bf<float,         true,  true,  true >, cudaFuncAttributeMaxDynamicSharedMemorySize, SMEM);

    dim3 blk(128);
    dim3 blk256(256);

    // setup: cvt x, cvt Wq|Wk|Wv, cvt Wo, pack bias
    {
        int n = MTOT * DIM;
        cvt_k<<<(n / 4 + 255) / 256, blk256>>>(x, xb, n);
        cvt_w3_k<<<3 * DIM * DIM / 4 / 256, blk256>>>(Wq, Wk, Wv, Wqkvb);
        cvt_k<<<DIM * DIM / 4 / 256, blk256>>>(Wo, Wob, DIM * DIM);
        pack_bias_k<<<NQKV / 256, blk256>>>(bq, bk, bv, bqkv);
    }

    // fused QKV projection: [16384,3072] = x @ Wqkv^T + bqkv (bf16 out)
    dim3 gQKV(NQKV / BN, MTOT / BM, 1);
    gemm_bf<__nv_bfloat16, true, false, true><<<gQKV, blk, SMEM>>>(xb, Wqkvb, bqkv, nullptr, QKV,
        DIM, DIM, NQKV, DIM, 1.f, 0, 0, 0);

    const __nv_bfloat16* Qv = QKV;
    const __nv_bfloat16* Kv = QKV + DIM;
    const __nv_bfloat16* Vv = QKV + 2 * DIM;

    // scores = Q K^T / 32 (fp32 out)
    dim3 gS_(SEQ / BN, SEQ / BM, BATCH);
    gemm_bf<float, false, false, true><<<gS_, blk, SMEM>>>(Qv, Kv, nullptr, nullptr, Sc,
        NQKV, NQKV, SEQ, DIM, 0.03125f,
        (long)SEQ * NQKV, (long)SEQ * NQKV, (long)SEQ * SEQ);

    // softmax (bf16 probs)
    softmax_k<<<BATCH * SEQ, blk256>>>(Sc, P);

    // weighted = P @ V (NN: V is [seq, dim] = [K, N] naturally; no transpose kernel)
    dim3 gW_(DIM / BN, SEQ / BM, BATCH);
    gemm_bf<__nv_bfloat16, false, false, false><<<gW_, blk, SMEM>>>(P, Vv, nullptr, nullptr, Wt,
        SEQ, NQKV, DIM, SEQ, 1.f,
        (long)SEQ * SEQ, (long)SEQ * NQKV, (long)SEQ * DIM);

    // out = weighted Wo^T + bo + x (fp32, residual fused)
    dim3 gO_(DIM / BN, MTOT / BM, 1);
    gemm_bf<float, true, true, true><<<gO_, blk, SMEM>>>(Wt, Wob, bo, x, out,
        DIM, DIM, DIM, DIM, 1.f, 0, 0, 0);

    // LayerNorm
    ln_k<<<MTOT, blk256>>>(out, gamma, beta);
}

// round 13
// speedup vs baseline: 1.0190x; 1.0190x over previous
#include <cuda_runtime.h>
#include <cuda_bf16.h>
#include <cstdint>
#include <cstddef>

#define BATCH 8
#define SEQ   2048
#define DIM   1024
#define MTOT  (BATCH*SEQ)   // 16384
#define NQKV  (3*DIM)       // 3072
#define KTILES (SEQ/128)    // 16 k-tiles per row

#define BM 128
#define BN 128
#define BK 64
#define KSTRIDE 72                        // NT: halves per smem row (64 data + 8 pad)
#define NSTRIDE 136                       // NN B tile: 128 cols + 8 pad
#define A_TILE_HALVES (BM*KSTRIDE)        // 9216
#define STAGE_HALVES (2*A_TILE_HALVES)
#define STAGE_BYTES (STAGE_HALVES*2)      // 36864
#define STAGES 3

// ---- scratch (device globals; allocation-free per harness rules) ----
__device__ __nv_bfloat16 g_xb[(size_t)MTOT*DIM];
__device__ __nv_bfloat16 g_Wqkvb[(size_t)NQKV*DIM];
__device__ __nv_bfloat16 g_Wob[DIM*DIM];
__device__ float         g_bqkv[NQKV];
__device__ __nv_bfloat16 g_QKV[(size_t)MTOT*NQKV];
__device__ __nv_bfloat16 g_P [(size_t)BATCH*SEQ*SEQ];
__device__ float         g_rpart[(size_t)BATCH*KTILES*SEQ];
__device__ float         g_rinv [(size_t)BATCH*SEQ];
__device__ __nv_bfloat16 g_Wt[(size_t)MTOT*DIM];

// ---- helpers ----
__device__ __forceinline__ void cp16(uint32_t saddr, const void* gmem) {
    asm volatile("cp.async.cg.shared.global [%0], [%1], 16;\n" :: "r"(saddr), "l"(gmem));
}
__device__ __forceinline__ void cp_commit() { asm volatile("cp.async.commit_group;\n"); }
template<int N> __device__ __forceinline__ void cp_wait() {
    asm volatile("cp.async.wait_group %0;\n" :: "n"(N));
}
__device__ __forceinline__ void ldsm_x4(uint32_t& r0, uint32_t& r1, uint32_t& r2, uint32_t& r3,
                                        uint32_t addr) {
    asm volatile("ldmatrix.sync.aligned.m8n8.x4.shared.b16 {%0,%1,%2,%3}, [%4];"
                 : "=r"(r0), "=r"(r1), "=r"(r2), "=r"(r3) : "r"(addr));
}
__device__ __forceinline__ void ldsm_x4_t(uint32_t& r0, uint32_t& r1, uint32_t& r2, uint32_t& r3,
                                          uint32_t addr) {
    asm volatile("ldmatrix.sync.aligned.m8n8.x4.trans.shared.b16 {%0,%1,%2,%3}, [%4];"
                 : "=r"(r0), "=r"(r1), "=r"(r2), "=r"(r3) : "r"(addr));
}
__device__ __forceinline__ void mma_bf16(float c[4], const uint32_t a[4], const uint32_t b[2]) {
    asm("mma.sync.aligned.m16n8k16.row.col.f32.bf16.bf16.f32 "
        "{%0,%1,%2,%3},{%4,%5,%6,%7},{%8,%9},{%0,%1,%2,%3};"
        : "+f"(c[0]), "+f"(c[1]), "+f"(c[2]), "+f"(c[3])
        : "r"(a[0]), "r"(a[1]), "r"(a[2]), "r"(a[3]), "r"(b[0]), "r"(b[1]));
}

// ---- bf16 GEMM: C = f(A[M,K] * op(B) * scale) (+bias) (+resid) ----
// TRANSB: B [N,K] (NT, ldmatrix) vs [K,N] (NN, ldmatrix.trans).
// EXP_OUT: C = exp(v); also writes deterministic per-row tile sums to rpart.
// ROW_DIV: C = v * rinv[row]  (post-PV softmax normalization).
template<typename OutT, bool HAS_BIAS, bool HAS_RESID, bool TRANSB, bool EXP_OUT, bool ROW_DIV>
__global__ __launch_bounds__(128, 2) void gemm_bf(
    const __nv_bfloat16* __restrict__ A, const __nv_bfloat16* __restrict__ B,
    const float* __restrict__ bias, const float* __restrict__ resid,
    OutT* __restrict__ C,
    int lda, int ldb, int ldc, int K, float scale,
    long sA, long sB, long sC,
    float* __restrict__ rpart, const float* __restrict__ rinv)
{
    extern __shared__ __align__(16) __nv_bfloat16 smem[];  // STAGES*(As+Bs)

    const int bz = blockIdx.z;
    A += (long)bz * sA;
    B += (long)bz * sB;
    C += (long)bz * sC;

    const int m0 = blockIdx.y * BM;
    const int n0 = blockIdx.x * BN;
    const int tid  = threadIdx.x;
    const int wid  = tid >> 5;
    const int lane = tid & 31;
    const int wm = (wid >> 1) * 64;   // 2 warps in m
    const int wn = (wid & 1) * 64;    // 2 warps in n
    const int lg = lane >> 2;
    const int lq = lane & 3;

    const int lr = tid >> 3;          // NT loader: 8 thr/row
    const int lc = (tid & 7) * 8;
    const int lr16 = tid >> 4;        // NN B loader: 16 thr/row
    const int lc16 = (tid & 15) * 8;

    const int a_row = wm + (lane & 15);
    const int a_ksel = (lane >> 4) * 8;
    const int b_row = wn + (lane & 7) + ((lane >> 4) & 1) * 8;
    const int b_ksel = ((lane >> 3) & 1) * 8;
    const int bt_krow = (lane & 7) + ((lane >> 3) & 1) * 8;
    const int bt_ncol = wn + ((lane >> 4) & 1) * 8;

    const uint32_t smem_base = (uint32_t)__cvta_generic_to_shared(smem);

    float acc[4][8][4];
#pragma unroll
    for (int i = 0; i < 4; i++)
#pragma unroll
        for (int j = 0; j < 8; j++)
#pragma unroll
            for (int r = 0; r < 4; r++) acc[i][j][r] = 0.f;

    const int KT = K / BK;

    auto load_stage = [&](int buf, int kt) {
        const int k0 = kt * BK;
        const uint32_t as = smem_base + buf * STAGE_BYTES;
        const uint32_t bs = as + A_TILE_HALVES * 2;
#pragma unroll
        for (int p = 0; p < 8; p++) {
            int row = lr + p * 16;
            cp16(as + (row * KSTRIDE + lc) * 2, A + (long)(m0 + row) * lda + k0 + lc);
        }
        if (TRANSB) {
#pragma unroll
            for (int p = 0; p < 8; p++) {
                int row = lr + p * 16;
                cp16(bs + (row * KSTRIDE + lc) * 2, B + (long)(n0 + row) * ldb + k0 + lc);
            }
        } else {
#pragma unroll
            for (int p = 0; p < 8; p++) {
                int row = lr16 + p * 8;
                cp16(bs + (row * NSTRIDE + lc16) * 2, B + (long)(k0 + row) * ldb + n0 + lc16);
            }
        }
        cp_commit();
    };

    load_stage(0, 0);
    load_stage(1, 1);

    for (int kt = 0; kt < KT; kt++) {
        const int buf = kt % STAGES;
        cp_wait<1>();
        __syncthreads();

        if (kt + 2 < KT) load_stage((kt + 2) % STAGES, kt + 2);

        const uint32_t as = smem_base + buf * STAGE_BYTES;
        const uint32_t bs = as + A_TILE_HALVES * 2;

#pragma unroll
        for (int s = 0; s < 4; s++) {
            uint32_t af[4][4];
            uint32_t bfr[8][2];
#pragma unroll
            for (int i = 0; i < 4; i++) {
                uint32_t addr = as + (((a_row + i * 16) * KSTRIDE) + s * 16 + a_ksel) * 2;
                ldsm_x4(af[i][0], af[i][1], af[i][2], af[i][3], addr);
            }
#pragma unroll
            for (int jp = 0; jp < 4; jp++) {
                if (TRANSB) {
                    uint32_t addr = bs + (((b_row + jp * 16) * KSTRIDE) + s * 16 + b_ksel) * 2;
                    ldsm_x4(bfr[jp * 2][0], bfr[jp * 2][1],
                            bfr[jp * 2 + 1][0], bfr[jp * 2 + 1][1], addr);
                } else {
                    uint32_t addr = bs + (((s * 16 + bt_krow) * NSTRIDE) + bt_ncol + jp * 16) * 2;
                    ldsm_x4_t(bfr[jp * 2][0], bfr[jp * 2][1],
                              bfr[jp * 2 + 1][0], bfr[jp * 2 + 1][1], addr);
                }
            }
#pragma unroll
            for (int i = 0; i < 4; i++)
#pragma unroll
                for (int j = 0; j < 8; j++)
                    mma_bf16(acc[i][j], af[i], bfr[j]);
        }
    }

    // epilogue
    float rs0[4], rs1[4];
#pragma unroll
    for (int i = 0; i < 4; i++) { rs0[i] = 0.f; rs1[i] = 0.f; }

#pragma unroll
    for (int i = 0; i < 4; i++) {
        int r = m0 + wm + i * 16 + lg;
        float ri0 = 1.f, ri1 = 1.f;
        if (ROW_DIV) {
            ri0 = rinv[(long)bz * SEQ + r];
            ri1 = rinv[(long)bz * SEQ + r + 8];
        }
#pragma unroll
        for (int j = 0; j < 8; j++) {
            int c = n0 + wn + j * 8 + lq * 2;
            float v0 = acc[i][j][0] * scale;
            float v1 = acc[i][j][1] * scale;
            float v2 = acc[i][j][2] * scale;
            float v3 = acc[i][j][3] * scale;
            if (HAS_BIAS) {
                float b0 = bias[c], b1 = bias[c + 1];
                v0 += b0; v1 += b1; v2 += b0; v3 += b1;
            }
            if (HAS_RESID) {
                v0 += resid[(long)r * ldc + c];
                v1 += resid[(long)r * ldc + c + 1];
                v2 += resid[(long)(r + 8) * ldc + c];
                v3 += resid[(long)(r + 8) * ldc + c + 1];
            }
            if (EXP_OUT) {
                v0 = __expf(v0); v1 = __expf(v1);
                v2 = __expf(v2); v3 = __expf(v3);
                rs0[i] += v0 + v1;
                rs1[i] += v2 + v3;
            }
            if (ROW_DIV) {
                v0 *= ri0; v1 *= ri0;
                v2 *= ri1; v3 *= ri1;
            }
            if constexpr (sizeof(OutT) == 2) {
                *reinterpret_cast<__nv_bfloat162*>(&C[(long)r * ldc + c]) =
                    __floats2bfloat162_rn(v0, v1);
                *reinterpret_cast<__nv_bfloat162*>(&C[(long)(r + 8) * ldc + c]) =
                    __floats2bfloat162_rn(v2, v3);
            } else {
                *reinterpret_cast<float2*>(&C[(long)r * ldc + c])       = make_float2(v0, v1);
                *reinterpret_cast<float2*>(&C[(long)(r + 8) * ldc + c]) = make_float2(v2, v3);
            }
        }
    }

    if (EXP_OUT) {
        // deterministic per-row tile sums: smem [128 rows][8 slots]
        float* sf = reinterpret_cast<float*>(smem);
        const int slot = (wid & 1) * 4 + lq;
        __syncthreads();   // done with pipeline smem
#pragma unroll
        for (int i = 0; i < 4; i++) {
            int rr = wm + i * 16 + lg;
            sf[rr * 8 + slot]       = rs0[i];
            sf[(rr + 8) * 8 + slot] = rs1[i];
        }
        __syncthreads();
        if (tid < 128) {
            float s = 0.f;
#pragma unroll
            for (int k = 0; k < 8; k++) s += sf[tid * 8 + k];
            rpart[((long)bz * gridDim.x + blockIdx.x) * SEQ + m0 + tid] = s;
        }
    }
}

// ---- rinv[b][r] = 1 / sum_kt rpart[b][kt][r] ----
__global__ __launch_bounds__(256) void rowinv_k(const float* __restrict__ rpart,
                                                float* __restrict__ rinv)
{
    int idx = blockIdx.x * 256 + threadIdx.x;   // 0..MTOT-1
    int b = idx / SEQ, r = idx % SEQ;
    float s = 0.f;
#pragma unroll
    for (int t = 0; t < KTILES; t++)
        s += rpart[((long)b * KTILES + t) * SEQ + r];
    rinv[idx] = 1.f / s;
}

// ---- fp32 -> bf16 convert ----
__global__ __launch_bounds__(256) void cvt_k(const float* __restrict__ in,
                                             __nv_bfloat16* __restrict__ out, int n)
{
    int i = (blockIdx.x * 256 + threadIdx.x) * 4;
    if (i < n) {
        float4 v = *reinterpret_cast<const float4*>(in + i);
        *reinterpret_cast<__nv_bfloat162*>(out + i)     = __floats2bfloat162_rn(v.x, v.y);
        *reinterpret_cast<__nv_bfloat162*>(out + i + 2) = __floats2bfloat162_rn(v.z, v.w);
    }
}

// ---- convert 3 weight matrices into concatenated bf16 buffer ----
__global__ __launch_bounds__(256) void cvt_w3_k(const float* __restrict__ w0,
                                                const float* __restrict__ w1,
                                                const float* __restrict__ w2,
                                                __nv_bfloat16* __restrict__ out)
{
    const int per = DIM * DIM / 4 / 256;
    const int mat = blockIdx.x / per;
    const int blk = blockIdx.x % per;
    const float* src = (mat == 0) ? w0 : (mat == 1) ? w1 : w2;
    int i = (blk * 256 + threadIdx.x) * 4;
    float4 v = *reinterpret_cast<const float4*>(src + i);
    __nv_bfloat16* dst = out + (size_t)mat * DIM * DIM + i;
    *reinterpret_cast<__nv_bfloat162*>(dst)     = __floats2bfloat162_rn(v.x, v.y);
    *reinterpret_cast<__nv_bfloat162*>(dst + 2) = __floats2bfloat162_rn(v.z, v.w);
}

// ---- pack 3 bias vectors into one ----
__global__ __launch_bounds__(256) void pack_bias_k(const float* __restrict__ b0,
                                                   const float* __restrict__ b1,
                                                   const float* __restrict__ b2,
                                                   float* __restrict__ out)
{
    int i = blockIdx.x * 256 + threadIdx.x;
    out[i] = (i < DIM) ? b0[i] : (i < 2 * DIM) ? b1[i - DIM] : b2[i - 2 * DIM];
}

// ---- in-place LayerNorm over rows of 1024 fp32 ----
__global__ __launch_bounds__(256) void ln_k(float* __restrict__ y,
                                            const float* __restrict__ gamma,
                                            const float* __restrict__ beta)
{
    float* p = y + (long)blockIdx.x * DIM;
    const int tid = threadIdx.x;
    float4 v = reinterpret_cast<float4*>(p)[tid];
    float s  = v.x + v.y + v.z + v.w;
    float sq = v.x * v.x + v.y * v.y + v.z * v.z + v.w * v.w;
#pragma unroll
    for (int o = 16; o; o >>= 1) {
        s  += __shfl_xor_sync(0xFFFFFFFFu, s, o);
        sq += __shfl_xor_sync(0xFFFFFFFFu, sq, o);
    }
    __shared__ float rs_[8], rq_[8];
    if ((tid & 31) == 0) { rs_[tid >> 5] = s; rq_[tid >> 5] = sq; }
    __syncthreads();
    s = 0.f; sq = 0.f;
#pragma unroll
    for (int i = 0; i < 8; i++) { s += rs_[i]; sq += rq_[i]; }
    const float mean = s * (1.f / DIM);
    const float var  = sq * (1.f / DIM) - mean * mean;
    const float inv  = rsqrtf(var + 1e-5f);
    const float4 g = reinterpret_cast<const float4*>(gamma)[tid];
    const float4 b = reinterpret_cast<const float4*>(beta)[tid];
    v.x = (v.x - mean) * inv * g.x + b.x;
    v.y = (v.y - mean) * inv * g.y + b.y;
    v.z = (v.z - mean) * inv * g.z + b.z;
    v.w = (v.w - mean) * inv * g.w + b.w;
    reinterpret_cast<float4*>(p)[tid] = v;
}

extern "C" void kernel_launch(void* const* d_in, const int* in_sizes, int n_in,
                              void* d_out, int out_size)
{
    const float* x     = (const float*)d_in[0];
    const float* Wq    = (const float*)d_in[1];
    const float* bq    = (const float*)d_in[2];
    const float* Wk    = (const float*)d_in[3];
    const float* bk    = (const float*)d_in[4];
    const float* Wv    = (const float*)d_in[5];
    const float* bv    = (const float*)d_in[6];
    const float* Wo    = (const float*)d_in[7];
    const float* bo    = (const float*)d_in[8];
    const float* gamma = (const float*)d_in[9];
    const float* beta  = (const float*)d_in[10];
    float* out = (float*)d_out;

    void *pxb, *pwqkv, *pwo, *pbqkv, *pQKV, *pP, *pW, *prp, *pri;
    cudaGetSymbolAddress(&pxb,   g_xb);
    cudaGetSymbolAddress(&pwqkv, g_Wqkvb);
    cudaGetSymbolAddress(&pwo,   g_Wob);
    cudaGetSymbolAddress(&pbqkv, g_bqkv);
    cudaGetSymbolAddress(&pQKV,  g_QKV);
    cudaGetSymbolAddress(&pP,    g_P);
    cudaGetSymbolAddress(&pW,    g_Wt);
    cudaGetSymbolAddress(&prp,   g_rpart);
    cudaGetSymbolAddress(&pri,   g_rinv);
    __nv_bfloat16* xb    = (__nv_bfloat16*)pxb;
    __nv_bfloat16* Wqkvb = (__nv_bfloat16*)pwqkv;
    __nv_bfloat16* Wob   = (__nv_bfloat16*)pwo;
    float*         bqkv  = (float*)pbqkv;
    __nv_bfloat16* QKV   = (__nv_bfloat16*)pQKV;
    __nv_bfloat16* P     = (__nv_bfloat16*)pP;
    __nv_bfloat16* Wt    = (__nv_bfloat16*)pW;
    float*         rpart = (float*)prp;
    float*         rinv  = (float*)pri;

    const int SMEM = STAGES * STAGE_BYTES;  // 110592
    cudaFuncSetAttribute((const void*)gemm_bf<__nv_bfloat16, true,  false, true,  false, false>, cudaFuncAttributeMaxDynamicSharedMemorySize, SMEM);
    cudaFuncSetAttribute((const void*)gemm_bf<__nv_bfloat16, false, false, true,  true,  false>, cudaFuncAttributeMaxDynamicSharedMemorySize, SMEM);
    cudaFuncSetAttribute((const void*)gemm_bf<__nv_bfloat16, false, false, false, false, true >, cudaFuncAttributeMaxDynamicSharedMemorySize, SMEM);
    cudaFuncSetAttribute((const void*)gemm_bf<float,         true,  true,  true,  false, false>, cudaFuncAttributeMaxDynamicSharedMemorySize, SMEM);

    dim3 blk(128);
    dim3 blk256(256);

    // setup
    {
        int n = MTOT * DIM;
        cvt_k<<<(n / 4 + 255) / 256, blk256>>>(x, xb, n);
        cvt_w3_k<<<3 * DIM * DIM / 4 / 256, blk256>>>(Wq, Wk, Wv, Wqkvb);
        cvt_k<<<DIM * DIM / 4 / 256, blk256>>>(Wo, Wob, DIM * DIM);
        pack_bias_k<<<NQKV / 256, blk256>>>(bq, bk, bv, bqkv);
    }

    // fused QKV projection (bf16 out)
    dim3 gQKV(NQKV / BN, MTOT / BM, 1);
    gemm_bf<__nv_bfloat16, true, false, true, false, false><<<gQKV, blk, SMEM>>>(
        xb, Wqkvb, bqkv, nullptr, QKV, DIM, DIM, NQKV, DIM, 1.f, 0, 0, 0, nullptr, nullptr);

    const __nv_bfloat16* Qv = QKV;
    const __nv_bfloat16* Kv = QKV + DIM;
    const __nv_bfloat16* Vv = QKV + 2 * DIM;

    // P_unnorm = exp(Q K^T / 32) (bf16), + per-row tile sums (no S buffer, no softmax kernel)
    dim3 gS_(SEQ / BN, SEQ / BM, BATCH);
    gemm_bf<__nv_bfloat16, false, false, true, true, false><<<gS_, blk, SMEM>>>(
        Qv, Kv, nullptr, nullptr, P, NQKV, NQKV, SEQ, DIM, 0.03125f,
        (long)SEQ * NQKV, (long)SEQ * NQKV, (long)SEQ * SEQ, rpart, nullptr);

    // rinv = 1 / row sums
    rowinv_k<<<MTOT / 256, blk256>>>(rpart, rinv);

    // weighted = (P_unnorm @ V) * rinv (NN path; normalization folded into epilogue)
    dim3 gW_(DIM / BN, SEQ / BM, BATCH);
    gemm_bf<__nv_bfloat16, false, false, false, false, true><<<gW_, blk, SMEM>>>(
        P, Vv, nullptr, nullptr, Wt, SEQ, NQKV, DIM, SEQ, 1.f,
        (long)SEQ * SEQ, (long)SEQ * NQKV, (long)SEQ * DIM, nullptr, rinv);

    // out = weighted Wo^T + bo + x (fp32, residual fused)
    dim3 gO_(DIM / BN, MTOT / BM, 1);
    gemm_bf<float, true, true, true, false, false><<<gO_, blk, SMEM>>>(
        Wt, Wob, bo, x, out, DIM, DIM, DIM, DIM, 1.f, 0, 0, 0, nullptr, nullptr);

    // LayerNorm
    ln_k<<<MTOT, blk256>>>(out, gamma, beta);
}